// round 14
// baseline (speedup 1.0000x reference)
#include <cuda_runtime.h>
#include <cuda_bf16.h>
#include <cstdint>

// PositionalEmbedding: out[l, :] = emb_table[token_ids[l], :] + PE(l, :)
// PE pairs p in [0,255): col 2p = sin(l / 10000^(2p/512)), col 2p+1 = cos(...).
// Cols 510, 511 get PE = 0 (reference only fills 255 pairs).
//
// cp.async-staged gather: each thread pipelines its 16B chunk of rows
// through an smem ring (STAGES=8) via cp.async.cg, decoupling in-flight
// read depth from register pressure (registers no longer hold the gathers,
// so occupancy and MLP stop trading off against each other). Each thread
// consumes exactly the chunks it staged -> no block synchronization.

#define SEQ   131072
#define DEPTH 512
#define ROWS_PER_GROUP 16   // rows per 128-thread group
#define STAGES 8            // cp.async ring depth (per thread)

// Per-pair frequency w_p = 10000^(2p/512), correctly-rounded fp32 (computed in
// double so it matches the reference's fp32 frequency to <=1ulp).
__device__ float g_w[256];

__global__ void setup_freq_kernel() {
    int p = threadIdx.x;
    if (p < 255) {
        double y = (double)(2 * p) / 512.0;          // exact in double
        double w = exp(y * 9.210340371976184);       // ln(10000)
        g_w[p] = (float)w;
    } else if (p == 255) {
        g_w[p] = 1.0f;  // unused (guarded)
    }
}

__device__ __forceinline__ void cp_async16(unsigned int smem_dst, const void* gmem_src) {
    asm volatile("cp.async.cg.shared.global [%0], [%1], 16;"
                 :: "r"(smem_dst), "l"(gmem_src) : "memory");
}
__device__ __forceinline__ void cp_commit() {
    asm volatile("cp.async.commit_group;" ::: "memory");
}
__device__ __forceinline__ void cp_wait7() {
    asm volatile("cp.async.wait_group 7;" ::: "memory");
}

// Accurate sin/cos of the fp32-rounded angle a = fl32(fi / w), mimicking
// jnp.sin/jnp.cos applied to the reference's fp32 angle.
//  - __fdiv_rn: IEEE round-to-nearest division (matches reference's angle bits)
//  - two-word Cody-Waite reduction mod 2pi (k <= 20861 for a <= 131071)
//  - MUFU sin/cos on the reduced argument |r| <= pi + 0.01
__device__ __forceinline__ float2 pe_pair(float fi, float w) {
    float a = __fdiv_rn(fi, w);
    float k = rintf(a * 0.15915494309189535f);
    // 2pi = HI + MID; HI = fl32(2pi), MID = 2pi - HI = -1.7484555e-7
    float r = fmaf(k, -6.283185307179586f, a);   // literal rounds to HI
    r = fmaf(k, 1.7484556e-07f, r);              // add back k*(HI - 2pi)
    float s, c;
    __sincosf(r, &s, &c);
    return make_float2(s, c);
}

__global__ void __launch_bounds__(256) emb_pe_kernel(
    const int*   __restrict__ tok,
    const float* __restrict__ tab,
    float*       __restrict__ out)
{
    // [group][stage][thread] : 2 * 8 * 128 * 16B = 32KB
    __shared__ float4 stage[2][STAGES][128];

    const int tid  = threadIdx.x;
    const unsigned t    = tid & 127;             // float4 index within a row
    const int grp  = tid >> 7;                   // 0 or 1
    const int base = (blockIdx.x * 2 + grp) * ROWS_PER_GROUP;

    // 32-bit byte offsets: table is 103MB, output 268MB — both < 4GB.
    const char* tabb = reinterpret_cast<const char*>(tab);
    char*       outb = reinterpret_cast<char*>(out);
    const unsigned tb = t << 4;                  // byte offset of this thread's float4

    // This thread's slot in stage s is at slot0 + s*2048 bytes.
    const unsigned int slot0 =
        (unsigned int)__cvta_generic_to_shared(&stage[grp][0][t]);

    // ---- prologue: fill the ring ----
#pragma unroll
    for (int s = 0; s < STAGES; s++) {
        const unsigned tk = (unsigned)__ldg(tok + base + s);
        cp_async16(slot0 + s * 2048u, tabb + ((tk << 11) + tb));
        cp_commit();
    }

    // frequencies for pairs p0 = 2t, p1 = 2t+1 — coalesced float2 load
    const float2 w    = __ldg(reinterpret_cast<const float2*>(g_w) + t);
    const bool   tail = (t == 127);              // pair 255 -> PE = 0

    unsigned ob = (((unsigned)base) << 11) + tb; // output byte offset, row 'base'

#pragma unroll
    for (int i = 0; i < ROWS_PER_GROUP; i++) {
        // Wait until <=7 groups outstanding: the group carrying row i is done.
        cp_wait7();
        const float4 e = stage[grp][i & (STAGES - 1)][t];

        // Refill the ring (empty commit in the tail keeps group accounting).
        const int nr = i + STAGES;
        if (nr < ROWS_PER_GROUP) {
            const unsigned tk = (unsigned)__ldg(tok + base + nr);
            cp_async16(slot0 + (unsigned)(nr & (STAGES - 1)) * 2048u,
                       tabb + ((tk << 11) + tb));
        }
        cp_commit();

        const float fi = (float)(base + i);
        float4 o;
        {
            float2 sc = pe_pair(fi, w.x);        // pair 2t (always < 255)
            o.x = e.x + sc.x;
            o.y = e.y + sc.y;
        }
        if (!tail) {
            float2 sc = pe_pair(fi, w.y);        // pair 2t+1
            o.z = e.z + sc.x;
            o.w = e.w + sc.y;
        } else {
            o.z = e.z;
            o.w = e.w;
        }
        // Streaming store: keep the 268MB output stream from displacing the
        // embedding table's L2 working set.
        __stcs(reinterpret_cast<float4*>(outb + ob), o);
        ob += 2048;                              // next row
    }
}

extern "C" void kernel_launch(void* const* d_in, const int* in_sizes, int n_in,
                              void* d_out, int out_size) {
    const int*   tok = (const int*)d_in[0];     // token_ids, int32 [131072]
    const float* tab = (const float*)d_in[1];   // emb_table, fp32 [50257, 512]
    float*       out = (float*)d_out;           // fp32 [131072, 512]

    setup_freq_kernel<<<1, 256>>>();
    emb_pe_kernel<<<SEQ / (2 * ROWS_PER_GROUP), 256>>>(tok, tab, out);
}

// round 16
// speedup vs baseline: 1.0299x; 1.0299x over previous
#include <cuda_runtime.h>
#include <cuda_bf16.h>

// PositionalEmbedding: out[l, :] = emb_table[token_ids[l], :] + PE(l, :)
// PE pairs p in [0,255): col 2p = sin(l / 10000^(2p/512)), col 2p+1 = cos(...).
// Cols 510, 511 get PE = 0 (reference only fills 255 pairs).
//
// FINAL (R7 structure, best-measured): 128 threads/row, float4 ld/st,
// 8 rows per 128-thread group with front-batched register gathers,
// __stcs streaming stores, 32-bit byte addressing.
//
// Falsified alternatives (kernel-time): 64thr/row+v8 bursts (67.0-67.6us),
// grid_constant freq table (68.1us), launch_bounds occ-force (68.7us),
// cp.async smem ring (68.3us), L2 evict_last (67.6us). This structure:
// 65.2us — at the HBM mixed random-read/stream-write ceiling (~73% of spec)
// with DRAM traffic within ~4% of the information-theoretic floor.

#define SEQ   131072
#define DEPTH 512
#define ROWS_PER_GROUP 8   // rows handled by each 128-thread group

// Per-pair frequency w_p = 10000^(2p/512), correctly-rounded fp32 (computed in
// double so it matches the reference's fp32 frequency to <=1ulp).
__device__ float g_w[256];

__global__ void setup_freq_kernel() {
    int p = threadIdx.x;
    if (p < 255) {
        double y = (double)(2 * p) / 512.0;          // exact in double
        double w = exp(y * 9.210340371976184);       // ln(10000)
        g_w[p] = (float)w;
    } else if (p == 255) {
        g_w[p] = 1.0f;  // unused (guarded)
    }
}

// Accurate sin/cos of the fp32-rounded angle a = fl32(fi / w), mimicking
// jnp.sin/jnp.cos applied to the reference's fp32 angle.
//  - __fdiv_rn: IEEE round-to-nearest division (matches reference's angle bits)
//  - two-word Cody-Waite reduction mod 2pi (k <= 20861 for a <= 131071)
//  - MUFU sin/cos on the reduced argument |r| <= pi + 0.01
__device__ __forceinline__ float2 pe_pair(float fi, float w) {
    float a = __fdiv_rn(fi, w);
    float k = rintf(a * 0.15915494309189535f);
    // 2pi = HI + MID; HI = fl32(2pi), MID = 2pi - HI = -1.7484555e-7
    float r = fmaf(k, -6.283185307179586f, a);   // literal rounds to HI
    r = fmaf(k, 1.7484556e-07f, r);              // add back k*(HI - 2pi)
    float s, c;
    __sincosf(r, &s, &c);
    return make_float2(s, c);
}

__global__ void __launch_bounds__(256) emb_pe_kernel(
    const int*   __restrict__ tok,
    const float* __restrict__ tab,
    float*       __restrict__ out)
{
    const int tid  = threadIdx.x;
    const unsigned t    = tid & 127;             // float4 index within a row
    const int grp  = tid >> 7;                   // 0 or 1
    const int base = (blockIdx.x * 2 + grp) * ROWS_PER_GROUP;

    // ---- 8 token ids via two coalesced int4 loads (base is 8-aligned) ----
    const int4 tka = __ldg(reinterpret_cast<const int4*>(tok + base));
    const int4 tkb = __ldg(reinterpret_cast<const int4*>(tok + base + 4));
    const unsigned tk[ROWS_PER_GROUP] = {
        (unsigned)tka.x, (unsigned)tka.y, (unsigned)tka.z, (unsigned)tka.w,
        (unsigned)tkb.x, (unsigned)tkb.y, (unsigned)tkb.z, (unsigned)tkb.w};

    // 32-bit byte offsets: table is 103MB, output 268MB — both < 4GB.
    const char* tabb = reinterpret_cast<const char*>(tab);
    char*       outb = reinterpret_cast<char*>(out);
    const unsigned tb = t << 4;                  // byte offset of this thread's float4

    // ---- front-batched independent table gathers (2KB-aligned rows) ----
    float4 e[ROWS_PER_GROUP];
#pragma unroll
    for (int r = 0; r < ROWS_PER_GROUP; r++)
        e[r] = __ldg(reinterpret_cast<const float4*>(tabb + ((tk[r] << 11) + tb)));

    // frequencies for pairs p0 = 2t, p1 = 2t+1 — coalesced float2 load
    const float2 w    = __ldg(reinterpret_cast<const float2*>(g_w) + t);
    const bool   tail = (t == 127);              // pair 255 -> PE = 0

    unsigned ob = (((unsigned)base) << 11) + tb; // output byte offset, row 'base'
#pragma unroll
    for (int r = 0; r < ROWS_PER_GROUP; r++) {
        const float fi = (float)(base + r);
        float4 o;
        {
            float2 sc = pe_pair(fi, w.x);        // pair 2t (always < 255)
            o.x = e[r].x + sc.x;
            o.y = e[r].y + sc.y;
        }
        if (!tail) {
            float2 sc = pe_pair(fi, w.y);        // pair 2t+1
            o.z = e[r].z + sc.x;
            o.w = e[r].w + sc.y;
        } else {
            o.z = e[r].z;
            o.w = e[r].w;
        }
        // Streaming store: keep the 268MB output stream from displacing the
        // embedding table's L2 working set.
        __stcs(reinterpret_cast<float4*>(outb + ob), o);
        ob += 2048;                              // next row
    }
}

extern "C" void kernel_launch(void* const* d_in, const int* in_sizes, int n_in,
                              void* d_out, int out_size) {
    const int*   tok = (const int*)d_in[0];     // token_ids, int32 [131072]
    const float* tab = (const float*)d_in[1];   // emb_table, fp32 [50257, 512]
    float*       out = (float*)d_out;           // fp32 [131072, 512]

    setup_freq_kernel<<<1, 256>>>();
    emb_pe_kernel<<<SEQ / (2 * ROWS_PER_GROUP), 256>>>(tok, tab, out);
}